// round 6
// baseline (speedup 1.0000x reference)
#include <cuda_runtime.h>
#include <cuda_fp16.h>
#include <math.h>

#define BB 4
#define SS 2048
#define EE 512
#define HH 8
#define DD 64
#define QP 72                     // smem pitch in halves (144B, conflict-free ldmatrix)
#define LOG2E8 0.18033688011112042f   // log2(e)/8

// ---------------------------------------------------------------------------
// Scratch (__device__ globals; allocation-free rule)
// ---------------------------------------------------------------------------
__device__ __align__(16) __half g_xh [BB*SS*EE];      // x fp16
__device__ __align__(16) __half g_wqh[3*EE*EE];       // Wqkv_w fp16
__device__ __align__(16) __half g_woh[EE*EE];         // out_w fp16
__device__ __align__(16) __half g_qh [BB*HH*SS*DD];   // q * log2e/8
__device__ __align__(16) __half g_kh [BB*HH*SS*DD];
__device__ __align__(16) __half g_vh [BB*HH*SS*DD];
__device__ __align__(16) __half g_oh [BB*SS*EE];      // attn out, [b*s, h*d]
__device__ __align__(16) unsigned g_adjbits[BB*SS*(SS/32)];

// ---------------------------------------------------------------------------
// PTX helpers
// ---------------------------------------------------------------------------
__device__ __forceinline__ unsigned smem_u32(const void* p) {
    unsigned a;
    asm("{ .reg .u64 t; cvta.to.shared.u64 t, %1; cvt.u32.u64 %0, t; }"
        : "=r"(a) : "l"(p));
    return a;
}

__device__ __forceinline__ void ldm_x4(unsigned* r, unsigned addr) {
    asm volatile("ldmatrix.sync.aligned.m8n8.x4.shared.b16 {%0,%1,%2,%3}, [%4];"
                 : "=r"(r[0]), "=r"(r[1]), "=r"(r[2]), "=r"(r[3]) : "r"(addr));
}

__device__ __forceinline__ void ldm_x4_t(unsigned* r, unsigned addr) {
    asm volatile("ldmatrix.sync.aligned.m8n8.x4.trans.shared.b16 {%0,%1,%2,%3}, [%4];"
                 : "=r"(r[0]), "=r"(r[1]), "=r"(r[2]), "=r"(r[3]) : "r"(addr));
}

__device__ __forceinline__ void mma16816(float* c, const unsigned* a,
                                         const unsigned* b) {
    asm volatile(
        "mma.sync.aligned.m16n8k16.row.col.f32.f16.f16.f32 "
        "{%0,%1,%2,%3}, {%4,%5,%6,%7}, {%8,%9}, {%0,%1,%2,%3};"
        : "+f"(c[0]), "+f"(c[1]), "+f"(c[2]), "+f"(c[3])
        : "r"(a[0]), "r"(a[1]), "r"(a[2]), "r"(a[3]), "r"(b[0]), "r"(b[1]));
}

__device__ __forceinline__ unsigned h2_exp2u(unsigned xi) {
    unsigned ri;
    asm("ex2.approx.f16x2 %0, %1;" : "=r"(ri) : "r"(xi));
    return ri;
}

__device__ __forceinline__ unsigned h2_pack(float a, float b) {
    __half2 h = __floats2half2_rn(a, b);
    return *reinterpret_cast<unsigned*>(&h);
}

#define CP_ASYNC(d, s) asm volatile("cp.async.cg.shared.global [%0], [%1], 16;" :: "r"(d), "l"(s))
#define CP_COMMIT()    asm volatile("cp.async.commit_group;")
#define CP_WAIT1()     asm volatile("cp.async.wait_group 1;")
#define CP_WAIT0()     asm volatile("cp.async.wait_group 0;")

// ---------------------------------------------------------------------------
// Kernel A: fp32 -> fp16 conversion for x, Wqkv_w, out_w
// ---------------------------------------------------------------------------
__global__ __launch_bounds__(256) void conv_kernel(
    const float* __restrict__ x, const float* __restrict__ wq,
    const float* __restrict__ wo)
{
    int idx = blockIdx.x * 256 + threadIdx.x;
    const float* src;
    __half* dst;
    if (idx < 524288)      { src = x  + (size_t)idx * 8;             dst = g_xh  + (size_t)idx * 8; }
    else if (idx < 622592) { src = wq + ((size_t)idx - 524288) * 8;  dst = g_wqh + ((size_t)idx - 524288) * 8; }
    else                   { src = wo + ((size_t)idx - 622592) * 8;  dst = g_woh + ((size_t)idx - 622592) * 8; }
    float4 f0 = *(const float4*)src;
    float4 f1 = *(const float4*)(src + 4);
    __half2 h[4] = {__floats2half2_rn(f0.x, f0.y), __floats2half2_rn(f0.z, f0.w),
                    __floats2half2_rn(f1.x, f1.y), __floats2half2_rn(f1.z, f1.w)};
    *(uint4*)dst = *(uint4*)h;
}

// ---------------------------------------------------------------------------
// Kernel B: pack adj into bitmask
// ---------------------------------------------------------------------------
__global__ __launch_bounds__(256) void adj_pack_kernel(const float* __restrict__ adj)
{
    size_t widx = (size_t)blockIdx.x * 8 + (threadIdx.x >> 5);
    unsigned lane = threadIdx.x & 31;
    float v = adj[widx * 32 + lane];
    unsigned bits = __ballot_sync(0xffffffffu, v != 0.0f);
    if (lane == 0) g_adjbits[widx] = bits;
}

// ---------------------------------------------------------------------------
// Kernel C: QKV projection, HMMA, 3-stage pipeline (unchanged from R5).
// ---------------------------------------------------------------------------
__global__ __launch_bounds__(256, 2) void qkv_hmma_kernel(const float* __restrict__ bias)
{
    extern __shared__ __align__(16) __half sm[];
    const unsigned sAb = smem_u32(sm);
    const unsigned sBb = sAb + 55296;

    const int tid = threadIdx.x;
    const int wid = tid >> 5, lane = tid & 31;
    const int gid = lane >> 2, tig = lane & 3, lr = lane & 7;
    const int m0 = blockIdx.y * 128, n0 = blockIdx.x * 64;

    const __half* A = g_xh;    // [8192,512]
    const __half* B = g_wqh;   // [1536,512]
    const int ar = tid >> 3, ac = tid & 7;

    #define QKV_ISSUE(kc, st) do { \
        unsigned da = sAb + (st) * 18432; \
        const __half* as = A + (size_t)(m0 + ar) * 512 + (kc) * 64 + ac * 8; \
        CP_ASYNC(da + (ar * QP + ac * 8) * 2, as); \
        CP_ASYNC(da + ((ar + 32) * QP + ac * 8) * 2, as + 32 * 512); \
        CP_ASYNC(da + ((ar + 64) * QP + ac * 8) * 2, as + 64 * 512); \
        CP_ASYNC(da + ((ar + 96) * QP + ac * 8) * 2, as + 96 * 512); \
        unsigned db = sBb + (st) * 9216; \
        const __half* bs = B + (size_t)(n0 + ar) * 512 + (kc) * 64 + ac * 8; \
        CP_ASYNC(db + (ar * QP + ac * 8) * 2, bs); \
        CP_ASYNC(db + ((ar + 32) * QP + ac * 8) * 2, bs + 32 * 512); \
    } while (0)

    const unsigned aq = ((wid * 16 + (lane & 15)) * QP + (lane >> 4) * 8) * 2;
    const unsigned bq = (((lane >> 4) * 8 + lr) * QP + ((lane >> 3) & 1) * 8) * 2;

    float c[8][4] = {};

    QKV_ISSUE(0, 0); CP_COMMIT();
    QKV_ISSUE(1, 1); CP_COMMIT();

    int st = 0, sti = 2;
    for (int kc = 0; kc < 8; kc++) {
        if (kc == 7) CP_WAIT0(); else CP_WAIT1();
        __syncthreads();
        if (kc < 6) { QKV_ISSUE(kc + 2, sti); CP_COMMIT(); }
        const unsigned ab = sAb + st * 18432;
        const unsigned bb = sBb + st * 9216;
        #pragma unroll
        for (int s = 0; s < 4; s++) {
            unsigned af[4];
            ldm_x4(af, ab + aq + s * 32);
            #pragma unroll
            for (int ntp = 0; ntp < 4; ntp++) {
                unsigned bf[4];
                ldm_x4(bf, bb + bq + ntp * (16 * QP * 2) + s * 32);
                mma16816(c[2 * ntp],     af, bf);
                mma16816(c[2 * ntp + 1], af, bf + 2);
            }
        }
        st = (st == 2) ? 0 : st + 1;
        sti = (sti == 2) ? 0 : sti + 1;
    }

    const int r0 = m0 + wid * 16 + gid;
    const int bi0 = r0 >> 11, si0 = r0 & 2047;
    const int r1 = r0 + 8;
    const int bi1 = r1 >> 11, si1 = r1 & 2047;
    #pragma unroll
    for (int nt = 0; nt < 8; nt++) {
        int col = n0 + nt * 8 + 2 * tig;
        float b0 = bias[col], b1 = bias[col + 1];
        int t = col >> 9, rem = col & 511;
        int hh = rem >> 6, di = rem & 63;
        float sc = (t == 0) ? LOG2E8 : 1.0f;
        __half2 h0 = __floats2half2_rn((c[nt][0] + b0) * sc, (c[nt][1] + b1) * sc);
        __half2 h1 = __floats2half2_rn((c[nt][2] + b0) * sc, (c[nt][3] + b1) * sc);
        size_t d0 = (((size_t)(bi0 * HH + hh) * SS) + si0) * DD + di;
        size_t d1 = (((size_t)(bi1 * HH + hh) * SS) + si1) * DD + di;
        __half* base = (t == 0) ? g_qh : (t == 1) ? g_kh : g_vh;
        *(__half2*)(base + d0) = h0;
        *(__half2*)(base + d1) = h1;
    }
}

// ---------------------------------------------------------------------------
// Kernel D: HMMA flash attention. BQ=128, BK=64. 8 warps tiled 4(q) x 2(kg):
// each warp computes 32 q-rows x 32 keys -> each K/V ldmatrix feeds 4 MMAs
// (2x fewer LDSM than M=16). Partial O/l reduced across kg pairs via smem
// once at the end. 3-stage cp.async, single sync per iter.
// Smem: Q 18432 + K 3x9216 + V 3x9216 = 73728 B.
// ---------------------------------------------------------------------------
__global__ __launch_bounds__(256) void attn_kernel()
{
    extern __shared__ __align__(16) __half sm[];
    const unsigned sQb = smem_u32(sm);
    const unsigned sKb = sQb + 18432;   // + st*9216
    const unsigned sVb = sQb + 46080;   // + st*9216

    const int tid = threadIdx.x;
    const int wid = tid >> 5, lane = tid & 31;
    const int gid = lane >> 2, tig = lane & 3, lr = lane & 7;
    const int qg = wid & 3, kg = wid >> 2;

    const int q0 = blockIdx.x * 128;
    const int hi = blockIdx.y, bi = blockIdx.z;
    const int bh = bi * HH + hi;

    const __half* Qg = g_qh + (size_t)bh * SS * DD;
    const __half* Kg = g_kh + (size_t)bh * SS * DD;
    const __half* Vg = g_vh + (size_t)bh * SS * DD;

    const int kr = tid >> 3, kc8 = tid & 7;

    #define KV_ISSUE(kt, st) do { \
        const __half* ks = Kg + (size_t)((kt) * 64 + kr) * DD + kc8 * 8; \
        const __half* vs = Vg + (size_t)((kt) * 64 + kr) * DD + kc8 * 8; \
        unsigned dk = sKb + (st) * 9216 + (kr * QP + kc8 * 8) * 2; \
        unsigned dv = sVb + (st) * 9216 + (kr * QP + kc8 * 8) * 2; \
        CP_ASYNC(dk, ks); \
        CP_ASYNC(dk + 32 * QP * 2, ks + 32 * DD); \
        CP_ASYNC(dv, vs); \
        CP_ASYNC(dv + 32 * QP * 2, vs + 32 * DD); \
    } while (0)

    // Q tile (plain stores)
    {
        const uint4* src = (const uint4*)(Qg + (size_t)q0 * DD);
        #pragma unroll
        for (int i = tid; i < 1024; i += 256) {
            int r = i >> 3, cc = i & 7;
            *(uint4*)(sm + r * QP + cc * 8) = src[r * 8 + cc];
        }
    }

    KV_ISSUE(0, 0); CP_COMMIT();
    KV_ISSUE(1, 1); CP_COMMIT();
    __syncthreads();   // covers Q stores

    // Q a-frags: 2 row-tiles x 4 k-steps
    unsigned qa[2][4][4];
    #pragma unroll
    for (int rt = 0; rt < 2; rt++) {
        int qrow = qg * 32 + rt * 16 + (lane & 15);
        int cofs = (lane >> 4) * 8;
        #pragma unroll
        for (int s = 0; s < 4; s++)
            ldm_x4(qa[rt][s], sQb + (qrow * QP + s * 16 + cofs) * 2);
    }

    const unsigned kq = (((lane >> 4) * 8 + lr) * QP + ((lane >> 3) & 1) * 8) * 2;
    const unsigned vq = ((((lane >> 3) & 1) * 8 + lr) * QP + (lane >> 4) * 8) * 2;

    // adjacency: one 32-bit word per (row, iter) — warp's 32 keys = 1 word
    const unsigned* mrow[2][2];
    {
        const unsigned* base = g_adjbits + ((size_t)bi * SS + q0 + qg * 32 + gid) * (SS / 32);
        mrow[0][0] = base;
        mrow[0][1] = base + 8  * (SS / 32);
        mrow[1][0] = base + 16 * (SS / 32);
        mrow[1][1] = base + 24 * (SS / 32);
    }

    const unsigned onesb[2] = {0x3C003C00u, 0x3C003C00u};  // fp16 {1,1}

    float oc[2][8][4] = {};
    float cl[2][4] = {};

    int st = 0, sti = 2;
    for (int kt = 0; kt < 32; kt++) {
        if (kt == 31) CP_WAIT0(); else CP_WAIT1();
        __syncthreads();
        if (kt < 30) { KV_ISSUE(kt + 2, sti); CP_COMMIT(); }

        const unsigned kb_base = sKb + st * 9216;
        const unsigned vb_base = sVb + st * 9216;

        // S(log2-domain) = Qs . K^T  (warp keys: kg*32 .. +32)
        float sc[2][4][4] = {};
        #pragma unroll
        for (int s = 0; s < 4; s++) {
            #pragma unroll
            for (int ntp = 0; ntp < 2; ntp++) {
                unsigned kb[4];
                ldm_x4(kb, kb_base + kq + (kg * 2 + ntp) * (16 * QP * 2) + s * 32);
                #pragma unroll
                for (int rt = 0; rt < 2; rt++) {
                    mma16816(sc[rt][2 * ntp],     qa[rt][s], kb);
                    mma16816(sc[rt][2 * ntp + 1], qa[rt][s], kb + 2);
                }
            }
        }

        // masked 2^s epilogue -> P a-frags
        const int widx = 2 * kt + kg;
        unsigned ph[2][4][2];
        #pragma unroll
        for (int rt = 0; rt < 2; rt++) {
            const unsigned wa = mrow[rt][0][widx];
            const unsigned wb = mrow[rt][1][widx];
            #pragma unroll
            for (int nt = 0; nt < 4; nt++) {
                int sh = nt * 8 + 2 * tig;
                unsigned ba  = (wa >> sh) & 3u;
                unsigned bb2 = (wb >> sh) & 3u;
                unsigned mA = ((ba & 1u) ? 0x0000FFFFu : 0u) | ((ba & 2u) ? 0xFFFF0000u : 0u);
                unsigned mB = ((bb2 & 1u) ? 0x0000FFFFu : 0u) | ((bb2 & 2u) ? 0xFFFF0000u : 0u);
                ph[rt][nt][0] = h2_exp2u(h2_pack(sc[rt][nt][0], sc[rt][nt][1]) & mA);
                ph[rt][nt][1] = h2_exp2u(h2_pack(sc[rt][nt][2], sc[rt][nt][3]) & mB);
            }
        }

        // O += P . V ; l += P . 1   (V rows: kg*32 + s2*16)
        #pragma unroll
        for (int s2 = 0; s2 < 2; s2++) {
            unsigned pa[2][4];
            #pragma unroll
            for (int rt = 0; rt < 2; rt++) {
                pa[rt][0] = ph[rt][2 * s2][0];     pa[rt][1] = ph[rt][2 * s2][1];
                pa[rt][2] = ph[rt][2 * s2 + 1][0]; pa[rt][3] = ph[rt][2 * s2 + 1][1];
                mma16816(cl[rt], pa[rt], onesb);
            }
            #pragma unroll
            for (int ntp = 0; ntp < 4; ntp++) {
                unsigned vb[4];
                ldm_x4_t(vb, vb_base + vq + (kg * 2 + s2) * (16 * QP * 2) + ntp * 32);
                #pragma unroll
                for (int rt = 0; rt < 2; rt++) {
                    mma16816(oc[rt][2 * ntp],     pa[rt], vb);
                    mma16816(oc[rt][2 * ntp + 1], pa[rt], vb + 2);
                }
            }
        }

        st = (st == 2) ? 0 : st + 1;
        sti = (sti == 2) ? 0 : sti + 1;
    }

    // ---- cross-kg reduction through smem (once per CTA) ----
    float* red  = (float*)sm;            // [128][64]
    float* redl = red + 128 * 64;        // [128]
    __syncthreads();
    if (kg == 1) {
        #pragma unroll
        for (int rt = 0; rt < 2; rt++) {
            int ra = qg * 32 + rt * 16 + gid;
            int rb = ra + 8;
            #pragma unroll
            for (int nt = 0; nt < 8; nt++) {
                int cc = nt * 8 + 2 * tig;
                *(float2*)&red[ra * 64 + cc] = make_float2(oc[rt][nt][0], oc[rt][nt][1]);
                *(float2*)&red[rb * 64 + cc] = make_float2(oc[rt][nt][2], oc[rt][nt][3]);
            }
            redl[ra] = cl[rt][0];
            redl[rb] = cl[rt][2];
        }
    }
    __syncthreads();
    if (kg == 0) {
        #pragma unroll
        for (int rt = 0; rt < 2; rt++) {
            int ra = qg * 32 + rt * 16 + gid;
            int rb = ra + 8;
            float inv_a = 1.0f / (cl[rt][0] + redl[ra]);
            float inv_b = 1.0f / (cl[rt][2] + redl[rb]);
            __half* oa = g_oh + ((size_t)bi * SS + q0 + ra) * EE + hi * 64;
            __half* ob = g_oh + ((size_t)bi * SS + q0 + rb) * EE + hi * 64;
            #pragma unroll
            for (int nt = 0; nt < 8; nt++) {
                int cc = nt * 8 + 2 * tig;
                float2 xa = *(float2*)&red[ra * 64 + cc];
                float2 xb = *(float2*)&red[rb * 64 + cc];
                *(__half2*)(oa + cc) = __floats2half2_rn((oc[rt][nt][0] + xa.x) * inv_a,
                                                         (oc[rt][nt][1] + xa.y) * inv_a);
                *(__half2*)(ob + cc) = __floats2half2_rn((oc[rt][nt][2] + xb.x) * inv_b,
                                                         (oc[rt][nt][3] + xb.y) * inv_b);
            }
        }
    }
}

// ---------------------------------------------------------------------------
// Kernel E: output projection, HMMA, 3-stage pipeline (unchanged from R5).
// ---------------------------------------------------------------------------
__global__ __launch_bounds__(256, 2) void out_hmma_kernel(
    const float* __restrict__ bias, float* __restrict__ out)
{
    extern __shared__ __align__(16) __half sm[];
    const unsigned sAb = smem_u32(sm);
    const unsigned sBb = sAb + 55296;

    const int tid = threadIdx.x;
    const int wid = tid >> 5, lane = tid & 31;
    const int gid = lane >> 2, tig = lane & 3, lr = lane & 7;
    const int m0 = blockIdx.y * 128, n0 = blockIdx.x * 64;

    const __half* A = g_oh;    // [8192,512]
    const __half* B = g_woh;   // [512,512]
    const int ar = tid >> 3, ac = tid & 7;

    #define OUT_ISSUE(kc, st) do { \
        unsigned da = sAb + (st) * 18432; \
        const __half* as = A + (size_t)(m0 + ar) * 512 + (kc) * 64 + ac * 8; \
        CP_ASYNC(da + (ar * QP + ac * 8) * 2, as); \
        CP_ASYNC(da + ((ar + 32) * QP + ac * 8) * 2, as + 32 * 512); \
        CP_ASYNC(da + ((ar + 64) * QP + ac * 8) * 2, as + 64 * 512); \
        CP_ASYNC(da + ((ar + 96) * QP + ac * 8) * 2, as + 96 * 512); \
        unsigned db = sBb + (st) * 9216; \
        const __half* bs = B + (size_t)(n0 + ar) * 512 + (kc) * 64 + ac * 8; \
        CP_ASYNC(db + (ar * QP + ac * 8) * 2, bs); \
        CP_ASYNC(db + ((ar + 32) * QP + ac * 8) * 2, bs + 32 * 512); \
    } while (0)

    const unsigned aq = ((wid * 16 + (lane & 15)) * QP + (lane >> 4) * 8) * 2;
    const unsigned bq = (((lane >> 4) * 8 + lr) * QP + ((lane >> 3) & 1) * 8) * 2;

    float c[8][4] = {};

    OUT_ISSUE(0, 0); CP_COMMIT();
    OUT_ISSUE(1, 1); CP_COMMIT();

    int st = 0, sti = 2;
    for (int kc = 0; kc < 8; kc++) {
        if (kc == 7) CP_WAIT0(); else CP_WAIT1();
        __syncthreads();
        if (kc < 6) { OUT_ISSUE(kc + 2, sti); CP_COMMIT(); }
        const unsigned ab = sAb + st * 18432;
        const unsigned bb = sBb + st * 9216;
        #pragma unroll
        for (int s = 0; s < 4; s++) {
            unsigned af[4];
            ldm_x4(af, ab + aq + s * 32);
            #pragma unroll
            for (int ntp = 0; ntp < 4; ntp++) {
                unsigned bf[4];
                ldm_x4(bf, bb + bq + ntp * (16 * QP * 2) + s * 32);
                mma16816(c[2 * ntp],     af, bf);
                mma16816(c[2 * ntp + 1], af, bf + 2);
            }
        }
        st = (st == 2) ? 0 : st + 1;
        sti = (sti == 2) ? 0 : sti + 1;
    }

    const int r0 = m0 + wid * 16 + gid;
    float* o0 = out + (size_t)r0 * EE;
    float* o1 = o0 + 8 * EE;
    #pragma unroll
    for (int nt = 0; nt < 8; nt++) {
        int col = n0 + nt * 8 + 2 * tig;
        float b0 = bias[col], b1 = bias[col + 1];
        *(float2*)(o0 + col) = make_float2(c[nt][0] + b0, c[nt][1] + b1);
        *(float2*)(o1 + col) = make_float2(c[nt][2] + b0, c[nt][3] + b1);
    }
}

// ---------------------------------------------------------------------------
// Launch
// ---------------------------------------------------------------------------
extern "C" void kernel_launch(void* const* d_in, const int* in_sizes, int n_in,
                              void* d_out, int out_size)
{
    const float* x      = (const float*)d_in[0];
    const float* adj    = (const float*)d_in[1];
    const float* Wqkv_w = (const float*)d_in[2];
    const float* Wqkv_b = (const float*)d_in[3];
    const float* out_w  = (const float*)d_in[4];
    const float* out_b  = (const float*)d_in[5];
    float* out = (float*)d_out;

    cudaFuncSetAttribute(qkv_hmma_kernel, cudaFuncAttributeMaxDynamicSharedMemorySize, 82944);
    cudaFuncSetAttribute(attn_kernel,     cudaFuncAttributeMaxDynamicSharedMemorySize, 73728);
    cudaFuncSetAttribute(out_hmma_kernel, cudaFuncAttributeMaxDynamicSharedMemorySize, 82944);

    conv_kernel<<<2560, 256>>>(x, Wqkv_w, out_w);
    adj_pack_kernel<<<BB * SS * (SS / 32) / 8, 256>>>(adj);
    qkv_hmma_kernel<<<dim3(24, 64), 256, 82944>>>(Wqkv_b);
    attn_kernel<<<dim3(SS / 128, HH, BB), 256, 73728>>>();
    out_hmma_kernel<<<dim3(8, 64), 256, 82944>>>(out_b, out);
}

// round 7
// speedup vs baseline: 1.0805x; 1.0805x over previous
#include <cuda_runtime.h>
#include <cuda_fp16.h>
#include <math.h>

#define BB 4
#define SS 2048
#define EE 512
#define HH 8
#define DD 64
#define QP 72                     // smem pitch in halves (144B, conflict-free ldmatrix)
#define LOG2E8 0.18033688011112042f   // log2(e)/8

// ---------------------------------------------------------------------------
// Scratch (__device__ globals; allocation-free rule)
// ---------------------------------------------------------------------------
__device__ __align__(16) __half g_xh [BB*SS*EE];      // x fp16
__device__ __align__(16) __half g_wqh[3*EE*EE];       // Wqkv_w fp16
__device__ __align__(16) __half g_woh[EE*EE];         // out_w fp16
__device__ __align__(16) __half g_qh [BB*HH*SS*DD];   // q * log2e/8
__device__ __align__(16) __half g_kh [BB*HH*SS*DD];
__device__ __align__(16) __half g_vh [BB*HH*SS*DD];
__device__ __align__(16) __half g_oh [BB*SS*EE];      // attn out, [b*s, h*d]
__device__ __align__(16) unsigned g_adjbits[BB*SS*(SS/32)];

// ---------------------------------------------------------------------------
// PTX helpers
// ---------------------------------------------------------------------------
__device__ __forceinline__ unsigned smem_u32(const void* p) {
    unsigned a;
    asm("{ .reg .u64 t; cvta.to.shared.u64 t, %1; cvt.u32.u64 %0, t; }"
        : "=r"(a) : "l"(p));
    return a;
}

__device__ __forceinline__ void ldm_x4(unsigned* r, unsigned addr) {
    asm volatile("ldmatrix.sync.aligned.m8n8.x4.shared.b16 {%0,%1,%2,%3}, [%4];"
                 : "=r"(r[0]), "=r"(r[1]), "=r"(r[2]), "=r"(r[3]) : "r"(addr));
}

__device__ __forceinline__ void ldm_x4_t(unsigned* r, unsigned addr) {
    asm volatile("ldmatrix.sync.aligned.m8n8.x4.trans.shared.b16 {%0,%1,%2,%3}, [%4];"
                 : "=r"(r[0]), "=r"(r[1]), "=r"(r[2]), "=r"(r[3]) : "r"(addr));
}

__device__ __forceinline__ void mma16816(float* c, const unsigned* a,
                                         const unsigned* b) {
    asm volatile(
        "mma.sync.aligned.m16n8k16.row.col.f32.f16.f16.f32 "
        "{%0,%1,%2,%3}, {%4,%5,%6,%7}, {%8,%9}, {%0,%1,%2,%3};"
        : "+f"(c[0]), "+f"(c[1]), "+f"(c[2]), "+f"(c[3])
        : "r"(a[0]), "r"(a[1]), "r"(a[2]), "r"(a[3]), "r"(b[0]), "r"(b[1]));
}

__device__ __forceinline__ unsigned h2_exp2u(unsigned xi) {
    unsigned ri;
    asm("ex2.approx.f16x2 %0, %1;" : "=r"(ri) : "r"(xi));
    return ri;
}

__device__ __forceinline__ unsigned h2_pack(float a, float b) {
    __half2 h = __floats2half2_rn(a, b);
    return *reinterpret_cast<unsigned*>(&h);
}

#define CP_ASYNC(d, s) asm volatile("cp.async.cg.shared.global [%0], [%1], 16;" :: "r"(d), "l"(s))
#define CP_COMMIT()    asm volatile("cp.async.commit_group;")
#define CP_WAIT1()     asm volatile("cp.async.wait_group 1;")
#define CP_WAIT0()     asm volatile("cp.async.wait_group 0;")

// ---------------------------------------------------------------------------
// Kernel A+B fused: adj bitmask pack + fp32->fp16 conversion.
// Blocks [0, 65536): adj pack. Blocks [65536, 68096): conversions.
// ---------------------------------------------------------------------------
__global__ __launch_bounds__(256) void prep_kernel(
    const float* __restrict__ adj, const float* __restrict__ x,
    const float* __restrict__ wq, const float* __restrict__ wo)
{
    if (blockIdx.x < 65536) {
        size_t widx = (size_t)blockIdx.x * 8 + (threadIdx.x >> 5);
        unsigned lane = threadIdx.x & 31;
        float v = adj[widx * 32 + lane];
        unsigned bits = __ballot_sync(0xffffffffu, v != 0.0f);
        if (lane == 0) g_adjbits[widx] = bits;
    } else {
        int idx = (blockIdx.x - 65536) * 256 + threadIdx.x;
        const float* src;
        __half* dst;
        if (idx < 524288)      { src = x  + (size_t)idx * 8;             dst = g_xh  + (size_t)idx * 8; }
        else if (idx < 622592) { src = wq + ((size_t)idx - 524288) * 8;  dst = g_wqh + ((size_t)idx - 524288) * 8; }
        else                   { src = wo + ((size_t)idx - 622592) * 8;  dst = g_woh + ((size_t)idx - 622592) * 8; }
        float4 f0 = *(const float4*)src;
        float4 f1 = *(const float4*)(src + 4);
        __half2 h[4] = {__floats2half2_rn(f0.x, f0.y), __floats2half2_rn(f0.z, f0.w),
                        __floats2half2_rn(f1.x, f1.y), __floats2half2_rn(f1.z, f1.w)};
        *(uint4*)dst = *(uint4*)h;
    }
}

// ---------------------------------------------------------------------------
// Kernel C: QKV projection, HMMA, 3-stage pipeline (R5-proven).
// ---------------------------------------------------------------------------
__global__ __launch_bounds__(256, 2) void qkv_hmma_kernel(const float* __restrict__ bias)
{
    extern __shared__ __align__(16) __half sm[];
    const unsigned sAb = smem_u32(sm);
    const unsigned sBb = sAb + 55296;

    const int tid = threadIdx.x;
    const int wid = tid >> 5, lane = tid & 31;
    const int gid = lane >> 2, tig = lane & 3, lr = lane & 7;
    const int m0 = blockIdx.y * 128, n0 = blockIdx.x * 64;

    const __half* A = g_xh;    // [8192,512]
    const __half* B = g_wqh;   // [1536,512]
    const int ar = tid >> 3, ac = tid & 7;

    #define QKV_ISSUE(kc, st) do { \
        unsigned da = sAb + (st) * 18432; \
        const __half* as = A + (size_t)(m0 + ar) * 512 + (kc) * 64 + ac * 8; \
        CP_ASYNC(da + (ar * QP + ac * 8) * 2, as); \
        CP_ASYNC(da + ((ar + 32) * QP + ac * 8) * 2, as + 32 * 512); \
        CP_ASYNC(da + ((ar + 64) * QP + ac * 8) * 2, as + 64 * 512); \
        CP_ASYNC(da + ((ar + 96) * QP + ac * 8) * 2, as + 96 * 512); \
        unsigned db = sBb + (st) * 9216; \
        const __half* bs = B + (size_t)(n0 + ar) * 512 + (kc) * 64 + ac * 8; \
        CP_ASYNC(db + (ar * QP + ac * 8) * 2, bs); \
        CP_ASYNC(db + ((ar + 32) * QP + ac * 8) * 2, bs + 32 * 512); \
    } while (0)

    const unsigned aq = ((wid * 16 + (lane & 15)) * QP + (lane >> 4) * 8) * 2;
    const unsigned bq = (((lane >> 4) * 8 + lr) * QP + ((lane >> 3) & 1) * 8) * 2;

    float c[8][4] = {};

    QKV_ISSUE(0, 0); CP_COMMIT();
    QKV_ISSUE(1, 1); CP_COMMIT();

    int st = 0, sti = 2;
    for (int kc = 0; kc < 8; kc++) {
        if (kc == 7) CP_WAIT0(); else CP_WAIT1();
        __syncthreads();
        if (kc < 6) { QKV_ISSUE(kc + 2, sti); CP_COMMIT(); }
        const unsigned ab = sAb + st * 18432;
        const unsigned bb = sBb + st * 9216;
        #pragma unroll
        for (int s = 0; s < 4; s++) {
            unsigned af[4];
            ldm_x4(af, ab + aq + s * 32);
            #pragma unroll
            for (int ntp = 0; ntp < 4; ntp++) {
                unsigned bf[4];
                ldm_x4(bf, bb + bq + ntp * (16 * QP * 2) + s * 32);
                mma16816(c[2 * ntp],     af, bf);
                mma16816(c[2 * ntp + 1], af, bf + 2);
            }
        }
        st = (st == 2) ? 0 : st + 1;
        sti = (sti == 2) ? 0 : sti + 1;
    }

    const int r0 = m0 + wid * 16 + gid;
    const int bi0 = r0 >> 11, si0 = r0 & 2047;
    const int r1 = r0 + 8;
    const int bi1 = r1 >> 11, si1 = r1 & 2047;
    #pragma unroll
    for (int nt = 0; nt < 8; nt++) {
        int col = n0 + nt * 8 + 2 * tig;
        float b0 = bias[col], b1 = bias[col + 1];
        int t = col >> 9, rem = col & 511;
        int hh = rem >> 6, di = rem & 63;
        float sc = (t == 0) ? LOG2E8 : 1.0f;
        __half2 h0 = __floats2half2_rn((c[nt][0] + b0) * sc, (c[nt][1] + b1) * sc);
        __half2 h1 = __floats2half2_rn((c[nt][2] + b0) * sc, (c[nt][3] + b1) * sc);
        size_t d0 = (((size_t)(bi0 * HH + hh) * SS) + si0) * DD + di;
        size_t d1 = (((size_t)(bi1 * HH + hh) * SS) + si1) * DD + di;
        __half* base = (t == 0) ? g_qh : (t == 1) ? g_kh : g_vh;
        *(__half2*)(base + d0) = h0;
        *(__half2*)(base + d1) = h1;
    }
}

// ---------------------------------------------------------------------------
// Kernel D: HMMA flash attention. BQ=64, BK=64, 8 warps = 4(qg) x 2(kg):
// each warp computes 16 q-rows x 32 keys. M=16/warp keeps regs ~115 (2 CTA/SM)
// while the kg split halves K/V LDSM per unit work vs R5. Cross-kg partial
// O/l reduction via smem once at the end. 3-stage cp.async, 1 sync/iter.
// Smem: Q 9216 + K 3x9216 + V 3x9216 = 64512 B.
// ---------------------------------------------------------------------------
__global__ __launch_bounds__(256, 2) void attn_kernel()
{
    extern __shared__ __align__(16) __half sm[];
    const unsigned sQb = smem_u32(sm);
    const unsigned sKb = sQb + 9216;    // + st*9216
    const unsigned sVb = sQb + 36864;   // + st*9216

    const int tid = threadIdx.x;
    const int wid = tid >> 5, lane = tid & 31;
    const int gid = lane >> 2, tig = lane & 3, lr = lane & 7;
    const int qg = wid & 3, kg = wid >> 2;

    const int q0 = blockIdx.x * 64;
    const int hi = blockIdx.y, bi = blockIdx.z;
    const int bh = bi * HH + hi;

    const __half* Qg = g_qh + (size_t)bh * SS * DD;
    const __half* Kg = g_kh + (size_t)bh * SS * DD;
    const __half* Vg = g_vh + (size_t)bh * SS * DD;

    const int kr = tid >> 3, kc8 = tid & 7;

    #define KV_ISSUE(kt, st) do { \
        const __half* ks = Kg + (size_t)((kt) * 64 + kr) * DD + kc8 * 8; \
        const __half* vs = Vg + (size_t)((kt) * 64 + kr) * DD + kc8 * 8; \
        unsigned dk = sKb + (st) * 9216 + (kr * QP + kc8 * 8) * 2; \
        unsigned dv = sVb + (st) * 9216 + (kr * QP + kc8 * 8) * 2; \
        CP_ASYNC(dk, ks); \
        CP_ASYNC(dk + 32 * QP * 2, ks + 32 * DD); \
        CP_ASYNC(dv, vs); \
        CP_ASYNC(dv + 32 * QP * 2, vs + 32 * DD); \
    } while (0)

    // Q tile: 64 rows (plain stores)
    {
        const uint4* src = (const uint4*)(Qg + (size_t)q0 * DD);
        #pragma unroll
        for (int i = tid; i < 512; i += 256) {
            int r = i >> 3, cc = i & 7;
            *(uint4*)(sm + r * QP + cc * 8) = src[r * 8 + cc];
        }
    }

    KV_ISSUE(0, 0); CP_COMMIT();
    KV_ISSUE(1, 1); CP_COMMIT();
    __syncthreads();   // covers Q stores

    // Q a-frags (16 rows per warp, 4 k-steps)
    unsigned qa[4][4];
    {
        int qrow = qg * 16 + (lane & 15);
        int cofs = (lane >> 4) * 8;
        #pragma unroll
        for (int s = 0; s < 4; s++)
            ldm_x4(qa[s], sQb + (qrow * QP + s * 16 + cofs) * 2);
    }

    const unsigned kq = (((lane >> 4) * 8 + lr) * QP + ((lane >> 3) & 1) * 8) * 2;
    const unsigned vq = ((((lane >> 3) & 1) * 8 + lr) * QP + (lane >> 4) * 8) * 2;

    // adjacency: warp's 32 keys = 1 word per row per iter
    const unsigned* mrow0 = g_adjbits + ((size_t)bi * SS + q0 + qg * 16 + gid) * (SS / 32);
    const unsigned* mrow1 = mrow0 + 8 * (SS / 32);

    const unsigned onesb[2] = {0x3C003C00u, 0x3C003C00u};  // fp16 {1,1}

    float oc[8][4] = {};
    float cl[4] = {};

    int st = 0, sti = 2;
    for (int kt = 0; kt < 32; kt++) {
        if (kt == 31) CP_WAIT0(); else CP_WAIT1();
        __syncthreads();
        if (kt < 30) { KV_ISSUE(kt + 2, sti); CP_COMMIT(); }

        const unsigned kb_base = sKb + st * 9216;
        const unsigned vb_base = sVb + st * 9216;

        // S(log2-domain) = Qs . K^T  (warp keys: kg*32 .. +32)
        float sc[4][4] = {};
        #pragma unroll
        for (int s = 0; s < 4; s++) {
            #pragma unroll
            for (int ntp = 0; ntp < 2; ntp++) {
                unsigned kb[4];
                ldm_x4(kb, kb_base + kq + (kg * 2 + ntp) * (16 * QP * 2) + s * 32);
                mma16816(sc[2 * ntp],     qa[s], kb);
                mma16816(sc[2 * ntp + 1], qa[s], kb + 2);
            }
        }

        // masked 2^s epilogue -> P a-frags
        const int widx = 2 * kt + kg;
        const unsigned wa = mrow0[widx];
        const unsigned wb = mrow1[widx];
        unsigned ph[4][2];
        #pragma unroll
        for (int nt = 0; nt < 4; nt++) {
            int sh = nt * 8 + 2 * tig;
            unsigned ba  = (wa >> sh) & 3u;
            unsigned bb2 = (wb >> sh) & 3u;
            unsigned mA = ((ba & 1u) ? 0x0000FFFFu : 0u) | ((ba & 2u) ? 0xFFFF0000u : 0u);
            unsigned mB = ((bb2 & 1u) ? 0x0000FFFFu : 0u) | ((bb2 & 2u) ? 0xFFFF0000u : 0u);
            ph[nt][0] = h2_exp2u(h2_pack(sc[nt][0], sc[nt][1]) & mA);
            ph[nt][1] = h2_exp2u(h2_pack(sc[nt][2], sc[nt][3]) & mB);
        }

        // O += P . V ; l += P . 1   (V rows: kg*32 + s2*16)
        #pragma unroll
        for (int s2 = 0; s2 < 2; s2++) {
            unsigned pa[4] = {ph[2 * s2][0], ph[2 * s2][1],
                              ph[2 * s2 + 1][0], ph[2 * s2 + 1][1]};
            mma16816(cl, pa, onesb);
            #pragma unroll
            for (int ntp = 0; ntp < 4; ntp++) {
                unsigned vb[4];
                ldm_x4_t(vb, vb_base + vq + (kg * 2 + s2) * (16 * QP * 2) + ntp * 32);
                mma16816(oc[2 * ntp],     pa, vb);
                mma16816(oc[2 * ntp + 1], pa, vb + 2);
            }
        }

        st = (st == 2) ? 0 : st + 1;
        sti = (sti == 2) ? 0 : sti + 1;
    }

    // ---- cross-kg reduction through smem (once per CTA) ----
    float* red  = (float*)sm;            // [64][64]
    float* redl = red + 64 * 64;         // [64]
    const int ra = qg * 16 + gid;
    const int rb = ra + 8;
    __syncthreads();
    if (kg == 1) {
        #pragma unroll
        for (int nt = 0; nt < 8; nt++) {
            int cc = nt * 8 + 2 * tig;
            *(float2*)&red[ra * 64 + cc] = make_float2(oc[nt][0], oc[nt][1]);
            *(float2*)&red[rb * 64 + cc] = make_float2(oc[nt][2], oc[nt][3]);
        }
        redl[ra] = cl[0];
        redl[rb] = cl[2];
    }
    __syncthreads();
    if (kg == 0) {
        float inv_a = 1.0f / (cl[0] + redl[ra]);
        float inv_b = 1.0f / (cl[2] + redl[rb]);
        __half* oa = g_oh + ((size_t)bi * SS + q0 + ra) * EE + hi * 64;
        __half* ob = g_oh + ((size_t)bi * SS + q0 + rb) * EE + hi * 64;
        #pragma unroll
        for (int nt = 0; nt < 8; nt++) {
            int cc = nt * 8 + 2 * tig;
            float2 xa = *(float2*)&red[ra * 64 + cc];
            float2 xb = *(float2*)&red[rb * 64 + cc];
            *(__half2*)(oa + cc) = __floats2half2_rn((oc[nt][0] + xa.x) * inv_a,
                                                     (oc[nt][1] + xa.y) * inv_a);
            *(__half2*)(ob + cc) = __floats2half2_rn((oc[nt][2] + xb.x) * inv_b,
                                                     (oc[nt][3] + xb.y) * inv_b);
        }
    }
}

// ---------------------------------------------------------------------------
// Kernel E: output projection, HMMA, 3-stage pipeline (R5-proven).
// ---------------------------------------------------------------------------
__global__ __launch_bounds__(256, 2) void out_hmma_kernel(
    const float* __restrict__ bias, float* __restrict__ out)
{
    extern __shared__ __align__(16) __half sm[];
    const unsigned sAb = smem_u32(sm);
    const unsigned sBb = sAb + 55296;

    const int tid = threadIdx.x;
    const int wid = tid >> 5, lane = tid & 31;
    const int gid = lane >> 2, tig = lane & 3, lr = lane & 7;
    const int m0 = blockIdx.y * 128, n0 = blockIdx.x * 64;

    const __half* A = g_oh;    // [8192,512]
    const __half* B = g_woh;   // [512,512]
    const int ar = tid >> 3, ac = tid & 7;

    #define OUT_ISSUE(kc, st) do { \
        unsigned da = sAb + (st) * 18432; \
        const __half* as = A + (size_t)(m0 + ar) * 512 + (kc) * 64 + ac * 8; \
        CP_ASYNC(da + (ar * QP + ac * 8) * 2, as); \
        CP_ASYNC(da + ((ar + 32) * QP + ac * 8) * 2, as + 32 * 512); \
        CP_ASYNC(da + ((ar + 64) * QP + ac * 8) * 2, as + 64 * 512); \
        CP_ASYNC(da + ((ar + 96) * QP + ac * 8) * 2, as + 96 * 512); \
        unsigned db = sBb + (st) * 9216; \
        const __half* bs = B + (size_t)(n0 + ar) * 512 + (kc) * 64 + ac * 8; \
        CP_ASYNC(db + (ar * QP + ac * 8) * 2, bs); \
        CP_ASYNC(db + ((ar + 32) * QP + ac * 8) * 2, bs + 32 * 512); \
    } while (0)

    const unsigned aq = ((wid * 16 + (lane & 15)) * QP + (lane >> 4) * 8) * 2;
    const unsigned bq = (((lane >> 4) * 8 + lr) * QP + ((lane >> 3) & 1) * 8) * 2;

    float c[8][4] = {};

    OUT_ISSUE(0, 0); CP_COMMIT();
    OUT_ISSUE(1, 1); CP_COMMIT();

    int st = 0, sti = 2;
    for (int kc = 0; kc < 8; kc++) {
        if (kc == 7) CP_WAIT0(); else CP_WAIT1();
        __syncthreads();
        if (kc < 6) { OUT_ISSUE(kc + 2, sti); CP_COMMIT(); }
        const unsigned ab = sAb + st * 18432;
        const unsigned bb = sBb + st * 9216;
        #pragma unroll
        for (int s = 0; s < 4; s++) {
            unsigned af[4];
            ldm_x4(af, ab + aq + s * 32);
            #pragma unroll
            for (int ntp = 0; ntp < 4; ntp++) {
                unsigned bf[4];
                ldm_x4(bf, bb + bq + ntp * (16 * QP * 2) + s * 32);
                mma16816(c[2 * ntp],     af, bf);
                mma16816(c[2 * ntp + 1], af, bf + 2);
            }
        }
        st = (st == 2) ? 0 : st + 1;
        sti = (sti == 2) ? 0 : sti + 1;
    }

    const int r0 = m0 + wid * 16 + gid;
    float* o0 = out + (size_t)r0 * EE;
    float* o1 = o0 + 8 * EE;
    #pragma unroll
    for (int nt = 0; nt < 8; nt++) {
        int col = n0 + nt * 8 + 2 * tig;
        float b0 = bias[col], b1 = bias[col + 1];
        *(float2*)(o0 + col) = make_float2(c[nt][0] + b0, c[nt][1] + b1);
        *(float2*)(o1 + col) = make_float2(c[nt][2] + b0, c[nt][3] + b1);
    }
}

// ---------------------------------------------------------------------------
// Launch
// ---------------------------------------------------------------------------
extern "C" void kernel_launch(void* const* d_in, const int* in_sizes, int n_in,
                              void* d_out, int out_size)
{
    const float* x      = (const float*)d_in[0];
    const float* adj    = (const float*)d_in[1];
    const float* Wqkv_w = (const float*)d_in[2];
    const float* Wqkv_b = (const float*)d_in[3];
    const float* out_w  = (const float*)d_in[4];
    const float* out_b  = (const float*)d_in[5];
    float* out = (float*)d_out;

    cudaFuncSetAttribute(qkv_hmma_kernel, cudaFuncAttributeMaxDynamicSharedMemorySize, 82944);
    cudaFuncSetAttribute(attn_kernel,     cudaFuncAttributeMaxDynamicSharedMemorySize, 64512);
    cudaFuncSetAttribute(out_hmma_kernel, cudaFuncAttributeMaxDynamicSharedMemorySize, 82944);

    prep_kernel<<<65536 + 2560, 256>>>(adj, x, Wqkv_w, out_w);
    qkv_hmma_kernel<<<dim3(24, 64), 256, 82944>>>(Wqkv_b);
    attn_kernel<<<dim3(SS / 64, HH, BB), 256, 64512>>>();
    out_hmma_kernel<<<dim3(8, 64), 256, 82944>>>(out_b, out);
}

// round 8
// speedup vs baseline: 1.2628x; 1.1687x over previous
#include <cuda_runtime.h>
#include <cuda_fp16.h>
#include <math.h>

#define BB 4
#define SS 2048
#define EE 512
#define HH 8
#define DD 64
#define QP 72                     // smem pitch in halves (144B, conflict-free ldmatrix)
#define LOG2E8 0.18033688011112042f   // log2(e)/8

// ---------------------------------------------------------------------------
// Scratch (__device__ globals; allocation-free rule)
// ---------------------------------------------------------------------------
__device__ __align__(16) __half g_xh [BB*SS*EE];      // x fp16
__device__ __align__(16) __half g_wqh[3*EE*EE];       // Wqkv_w fp16
__device__ __align__(16) __half g_woh[EE*EE];         // out_w fp16
__device__ __align__(16) __half g_qh [BB*HH*SS*DD];   // q * log2e/8
__device__ __align__(16) __half g_kh [BB*HH*SS*DD];
__device__ __align__(16) __half g_vh [BB*HH*SS*DD];
__device__ __align__(16) __half g_oh [BB*SS*EE];      // attn out, [b*s, h*d]
__device__ __align__(16) unsigned g_adjbits[BB*SS*(SS/32)];

// ---------------------------------------------------------------------------
// PTX helpers
// ---------------------------------------------------------------------------
__device__ __forceinline__ unsigned smem_u32(const void* p) {
    unsigned a;
    asm("{ .reg .u64 t; cvta.to.shared.u64 t, %1; cvt.u32.u64 %0, t; }"
        : "=r"(a) : "l"(p));
    return a;
}

__device__ __forceinline__ void ldm_x4(unsigned* r, unsigned addr) {
    asm volatile("ldmatrix.sync.aligned.m8n8.x4.shared.b16 {%0,%1,%2,%3}, [%4];"
                 : "=r"(r[0]), "=r"(r[1]), "=r"(r[2]), "=r"(r[3]) : "r"(addr));
}

__device__ __forceinline__ void ldm_x4_t(unsigned* r, unsigned addr) {
    asm volatile("ldmatrix.sync.aligned.m8n8.x4.trans.shared.b16 {%0,%1,%2,%3}, [%4];"
                 : "=r"(r[0]), "=r"(r[1]), "=r"(r[2]), "=r"(r[3]) : "r"(addr));
}

__device__ __forceinline__ void mma16816(float* c, const unsigned* a,
                                         const unsigned* b) {
    asm volatile(
        "mma.sync.aligned.m16n8k16.row.col.f32.f16.f16.f32 "
        "{%0,%1,%2,%3}, {%4,%5,%6,%7}, {%8,%9}, {%0,%1,%2,%3};"
        : "+f"(c[0]), "+f"(c[1]), "+f"(c[2]), "+f"(c[3])
        : "r"(a[0]), "r"(a[1]), "r"(a[2]), "r"(a[3]), "r"(b[0]), "r"(b[1]));
}

__device__ __forceinline__ unsigned h2_exp2u(unsigned xi) {
    unsigned ri;
    asm("ex2.approx.f16x2 %0, %1;" : "=r"(ri) : "r"(xi));
    return ri;
}

__device__ __forceinline__ unsigned h2_pack(float a, float b) {
    __half2 h = __floats2half2_rn(a, b);
    return *reinterpret_cast<unsigned*>(&h);
}

#define CP_ASYNC(d, s) asm volatile("cp.async.cg.shared.global [%0], [%1], 16;" :: "r"(d), "l"(s))
#define CP_COMMIT()    asm volatile("cp.async.commit_group;")
#define CP_WAIT1()     asm volatile("cp.async.wait_group 1;")
#define CP_WAIT0()     asm volatile("cp.async.wait_group 0;")

// ---------------------------------------------------------------------------
// Kernel A: fp32 -> fp16 conversion for x, Wqkv_w, out_w
// ---------------------------------------------------------------------------
__global__ __launch_bounds__(256) void conv_kernel(
    const float* __restrict__ x, const float* __restrict__ wq,
    const float* __restrict__ wo)
{
    int idx = blockIdx.x * 256 + threadIdx.x;
    const float* src;
    __half* dst;
    if (idx < 524288)      { src = x  + (size_t)idx * 8;             dst = g_xh  + (size_t)idx * 8; }
    else if (idx < 622592) { src = wq + ((size_t)idx - 524288) * 8;  dst = g_wqh + ((size_t)idx - 524288) * 8; }
    else                   { src = wo + ((size_t)idx - 622592) * 8;  dst = g_woh + ((size_t)idx - 622592) * 8; }
    float4 f0 = *(const float4*)src;
    float4 f1 = *(const float4*)(src + 4);
    __half2 h[4] = {__floats2half2_rn(f0.x, f0.y), __floats2half2_rn(f0.z, f0.w),
                    __floats2half2_rn(f1.x, f1.y), __floats2half2_rn(f1.z, f1.w)};
    *(uint4*)dst = *(uint4*)h;
}

// ---------------------------------------------------------------------------
// Kernel C: fused QKV projection + adj bitmask pack.
// Grid 2048: CTAs with (blockIdx&3)==3 pack a 1024-word chunk of adj
// (interleaved so the DRAM stream overlaps the tensor-bound GEMM CTAs);
// the other 1536 CTAs run the R5-proven HMMA GEMM (BM=128, BN=64, 3-stage).
// ---------------------------------------------------------------------------
__global__ __launch_bounds__(256, 2) void qkvpack_kernel(
    const float* __restrict__ bias, const float* __restrict__ adj)
{
    // ---- adj pack role ----
    if ((blockIdx.x & 3) == 3) {
        const int p = blockIdx.x >> 2;             // 0..511
        const int wid = threadIdx.x >> 5, lane = threadIdx.x & 31;
        // warp packs 128 words = 32 steps x (128 floats -> 4 words)
        const float* basef = adj + ((size_t)p * 1024 + wid * 128) * 32;
        unsigned* outw = g_adjbits + p * 1024 + wid * 128;
        #pragma unroll 4
        for (int s = 0; s < 32; s++) {
            const float* src = basef + (size_t)s * 128;
            float v0 = src[lane];
            float v1 = src[lane + 32];
            float v2 = src[lane + 64];
            float v3 = src[lane + 96];
            unsigned w0 = __ballot_sync(0xffffffffu, v0 != 0.0f);
            unsigned w1 = __ballot_sync(0xffffffffu, v1 != 0.0f);
            unsigned w2 = __ballot_sync(0xffffffffu, v2 != 0.0f);
            unsigned w3 = __ballot_sync(0xffffffffu, v3 != 0.0f);
            if (lane == 0) {
                uint4 w = make_uint4(w0, w1, w2, w3);
                *(uint4*)(outw + s * 4) = w;
            }
        }
        return;
    }

    // ---- GEMM role ----
    const int g = (blockIdx.x >> 2) * 3 + (blockIdx.x & 3);   // 0..1535
    const int m0 = (g / 24) * 128, n0 = (g % 24) * 64;

    extern __shared__ __align__(16) __half sm[];
    const unsigned sAb = smem_u32(sm);
    const unsigned sBb = sAb + 55296;

    const int tid = threadIdx.x;
    const int wid = tid >> 5, lane = tid & 31;
    const int gid = lane >> 2, tig = lane & 3, lr = lane & 7;

    const __half* A = g_xh;    // [8192,512]
    const __half* B = g_wqh;   // [1536,512]
    const int ar = tid >> 3, ac = tid & 7;

    #define QKV_ISSUE(kc, st) do { \
        unsigned da = sAb + (st) * 18432; \
        const __half* as = A + (size_t)(m0 + ar) * 512 + (kc) * 64 + ac * 8; \
        CP_ASYNC(da + (ar * QP + ac * 8) * 2, as); \
        CP_ASYNC(da + ((ar + 32) * QP + ac * 8) * 2, as + 32 * 512); \
        CP_ASYNC(da + ((ar + 64) * QP + ac * 8) * 2, as + 64 * 512); \
        CP_ASYNC(da + ((ar + 96) * QP + ac * 8) * 2, as + 96 * 512); \
        unsigned db = sBb + (st) * 9216; \
        const __half* bs = B + (size_t)(n0 + ar) * 512 + (kc) * 64 + ac * 8; \
        CP_ASYNC(db + (ar * QP + ac * 8) * 2, bs); \
        CP_ASYNC(db + ((ar + 32) * QP + ac * 8) * 2, bs + 32 * 512); \
    } while (0)

    const unsigned aq = ((wid * 16 + (lane & 15)) * QP + (lane >> 4) * 8) * 2;
    const unsigned bq = (((lane >> 4) * 8 + lr) * QP + ((lane >> 3) & 1) * 8) * 2;

    float c[8][4] = {};

    QKV_ISSUE(0, 0); CP_COMMIT();
    QKV_ISSUE(1, 1); CP_COMMIT();

    int st = 0, sti = 2;
    for (int kc = 0; kc < 8; kc++) {
        if (kc == 7) CP_WAIT0(); else CP_WAIT1();
        __syncthreads();
        if (kc < 6) { QKV_ISSUE(kc + 2, sti); CP_COMMIT(); }
        const unsigned ab = sAb + st * 18432;
        const unsigned bb = sBb + st * 9216;
        #pragma unroll
        for (int s = 0; s < 4; s++) {
            unsigned af[4];
            ldm_x4(af, ab + aq + s * 32);
            #pragma unroll
            for (int ntp = 0; ntp < 4; ntp++) {
                unsigned bf[4];
                ldm_x4(bf, bb + bq + ntp * (16 * QP * 2) + s * 32);
                mma16816(c[2 * ntp],     af, bf);
                mma16816(c[2 * ntp + 1], af, bf + 2);
            }
        }
        st = (st == 2) ? 0 : st + 1;
        sti = (sti == 2) ? 0 : sti + 1;
    }

    const int r0 = m0 + wid * 16 + gid;
    const int bi0 = r0 >> 11, si0 = r0 & 2047;
    const int r1 = r0 + 8;
    const int bi1 = r1 >> 11, si1 = r1 & 2047;
    #pragma unroll
    for (int nt = 0; nt < 8; nt++) {
        int col = n0 + nt * 8 + 2 * tig;
        float b0 = bias[col], b1 = bias[col + 1];
        int t = col >> 9, rem = col & 511;
        int hh = rem >> 6, di = rem & 63;
        float sc = (t == 0) ? LOG2E8 : 1.0f;
        __half2 h0 = __floats2half2_rn((c[nt][0] + b0) * sc, (c[nt][1] + b1) * sc);
        __half2 h1 = __floats2half2_rn((c[nt][2] + b0) * sc, (c[nt][3] + b1) * sc);
        size_t d0 = (((size_t)(bi0 * HH + hh) * SS) + si0) * DD + di;
        size_t d1 = (((size_t)(bi1 * HH + hh) * SS) + si1) * DD + di;
        __half* base = (t == 0) ? g_qh : (t == 1) ? g_kh : g_vh;
        *(__half2*)(base + d0) = h0;
        *(__half2*)(base + d1) = h1;
    }
}

// ---------------------------------------------------------------------------
// Kernel D: HMMA flash attention — exact R5 kernel (best measured: 129.5us).
// BQ=128, BK=64, 8 warps x 16 rows, 3-stage cp.async, l via ones-MMA,
// half-domain masked ex2. Smem: Q 18432 + K 3x9216 + V 3x9216 = 73728 B.
// ---------------------------------------------------------------------------
__global__ __launch_bounds__(256, 2) void attn_kernel()
{
    extern __shared__ __align__(16) __half sm[];
    const unsigned sQb = smem_u32(sm);
    const unsigned sKb = sQb + 18432;   // + st*9216
    const unsigned sVb = sQb + 46080;   // + st*9216

    const int tid = threadIdx.x;
    const int wid = tid >> 5, lane = tid & 31;
    const int gid = lane >> 2, tig = lane & 3, lr = lane & 7;

    const int q0 = blockIdx.x * 128;
    const int hi = blockIdx.y, bi = blockIdx.z;
    const int bh = bi * HH + hi;

    const __half* Qg = g_qh + (size_t)bh * SS * DD;
    const __half* Kg = g_kh + (size_t)bh * SS * DD;
    const __half* Vg = g_vh + (size_t)bh * SS * DD;

    const int kr = tid >> 3, kc8 = tid & 7;

    #define KV_ISSUE(kt, st) do { \
        const __half* ks = Kg + (size_t)((kt) * 64 + kr) * DD + kc8 * 8; \
        const __half* vs = Vg + (size_t)((kt) * 64 + kr) * DD + kc8 * 8; \
        unsigned dk = sKb + (st) * 9216 + (kr * QP + kc8 * 8) * 2; \
        unsigned dv = sVb + (st) * 9216 + (kr * QP + kc8 * 8) * 2; \
        CP_ASYNC(dk, ks); \
        CP_ASYNC(dk + 32 * QP * 2, ks + 32 * DD); \
        CP_ASYNC(dv, vs); \
        CP_ASYNC(dv + 32 * QP * 2, vs + 32 * DD); \
    } while (0)

    // Q tile (plain stores)
    {
        const uint4* src = (const uint4*)(Qg + (size_t)q0 * DD);
        #pragma unroll
        for (int i = tid; i < 1024; i += 256) {
            int r = i >> 3, cc = i & 7;
            *(uint4*)(sm + r * QP + cc * 8) = src[r * 8 + cc];
        }
    }

    KV_ISSUE(0, 0); CP_COMMIT();
    KV_ISSUE(1, 1); CP_COMMIT();
    __syncthreads();   // covers Q stores

    // Q a-frags (registers, reused all 32 iters)
    unsigned qa[4][4];
    {
        int qrow = wid * 16 + (lane & 15);
        int cofs = (lane >> 4) * 8;
        #pragma unroll
        for (int s = 0; s < 4; s++)
            ldm_x4(qa[s], sQb + (qrow * QP + s * 16 + cofs) * 2);
    }

    const unsigned kq = (((lane >> 4) * 8 + lr) * QP + ((lane >> 3) & 1) * 8) * 2;
    const unsigned vq = ((((lane >> 3) & 1) * 8 + lr) * QP + (lane >> 4) * 8) * 2;

    const int r0g = q0 + wid * 16 + gid;
    const unsigned* m0p = g_adjbits + ((size_t)bi * SS + r0g) * (SS / 32);
    const unsigned* m1p = m0p + 8 * (SS / 32);

    const unsigned onesb[2] = {0x3C003C00u, 0x3C003C00u};  // fp16 {1,1}

    float oc[8][4] = {};
    float cl[4] = {};              // l row-sums via MMA

    int st = 0, sti = 2;
    for (int kt = 0; kt < 32; kt++) {
        if (kt == 31) CP_WAIT0(); else CP_WAIT1();
        __syncthreads();
        if (kt < 30) { KV_ISSUE(kt + 2, sti); CP_COMMIT(); }

        const unsigned kb_base = sKb + st * 9216;
        const unsigned vb_base = sVb + st * 9216;

        // S(log2-domain) = Qs . K^T
        float sc[8][4] = {};
        #pragma unroll
        for (int s = 0; s < 4; s++) {
            #pragma unroll
            for (int ntp = 0; ntp < 4; ntp++) {
                unsigned kb[4];
                ldm_x4(kb, kb_base + kq + ntp * (16 * QP * 2) + s * 32);
                mma16816(sc[2 * ntp],     qa[s], kb);
                mma16816(sc[2 * ntp + 1], qa[s], kb + 2);
            }
        }

        // masked 2^s epilogue in half domain -> P a-frags
        const uint2 wv0 = *(const uint2*)(m0p + 2 * kt);
        const uint2 wv1 = *(const uint2*)(m1p + 2 * kt);
        unsigned ph[8][2];
        #pragma unroll
        for (int nt = 0; nt < 8; nt++) {
            int cb = nt * 8 + 2 * tig;
            unsigned wa = (cb < 32) ? wv0.x : wv0.y;
            unsigned wb = (cb < 32) ? wv1.x : wv1.y;
            int sh = cb & 31;
            unsigned ba = (wa >> sh) & 3u;
            unsigned bb2 = (wb >> sh) & 3u;
            unsigned mA = ((ba & 1u) ? 0x0000FFFFu : 0u) | ((ba & 2u) ? 0xFFFF0000u : 0u);
            unsigned mB = ((bb2 & 1u) ? 0x0000FFFFu : 0u) | ((bb2 & 2u) ? 0xFFFF0000u : 0u);
            ph[nt][0] = h2_exp2u(h2_pack(sc[nt][0], sc[nt][1]) & mA);
            ph[nt][1] = h2_exp2u(h2_pack(sc[nt][2], sc[nt][3]) & mB);
        }

        // O += P . V ; l += P . 1
        #pragma unroll
        for (int s = 0; s < 4; s++) {
            unsigned pa[4] = {ph[2 * s][0], ph[2 * s][1],
                              ph[2 * s + 1][0], ph[2 * s + 1][1]};
            mma16816(cl, pa, onesb);
            #pragma unroll
            for (int ntp = 0; ntp < 4; ntp++) {
                unsigned vb[4];
                ldm_x4_t(vb, vb_base + vq + s * (16 * QP * 2) + ntp * 32);
                mma16816(oc[2 * ntp],     pa, vb);
                mma16816(oc[2 * ntp + 1], pa, vb + 2);
            }
        }

        st = (st == 2) ? 0 : st + 1;
        sti = (sti == 2) ? 0 : sti + 1;
    }

    const float inv0 = 1.0f / cl[0], inv1 = 1.0f / cl[2];

    __half* o0 = g_oh + ((size_t)bi * SS + r0g) * EE + hi * 64;
    __half* o1 = o0 + 8 * EE;
    #pragma unroll
    for (int nt = 0; nt < 8; nt++) {
        int cc = nt * 8 + 2 * tig;
        *(__half2*)(o0 + cc) = __floats2half2_rn(oc[nt][0] * inv0, oc[nt][1] * inv0);
        *(__half2*)(o1 + cc) = __floats2half2_rn(oc[nt][2] * inv1, oc[nt][3] * inv1);
    }
}

// ---------------------------------------------------------------------------
// Kernel E: output projection, HMMA, 3-stage pipeline (R5-proven).
// ---------------------------------------------------------------------------
__global__ __launch_bounds__(256, 2) void out_hmma_kernel(
    const float* __restrict__ bias, float* __restrict__ out)
{
    extern __shared__ __align__(16) __half sm[];
    const unsigned sAb = smem_u32(sm);
    const unsigned sBb = sAb + 55296;

    const int tid = threadIdx.x;
    const int wid = tid >> 5, lane = tid & 31;
    const int gid = lane >> 2, tig = lane & 3, lr = lane & 7;
    const int m0 = blockIdx.y * 128, n0 = blockIdx.x * 64;

    const __half* A = g_oh;    // [8192,512]
    const __half* B = g_woh;   // [512,512]
    const int ar = tid >> 3, ac = tid & 7;

    #define OUT_ISSUE(kc, st) do { \
        unsigned da = sAb + (st) * 18432; \
        const __half* as = A + (size_t)(m0 + ar) * 512 + (kc) * 64 + ac * 8; \
        CP_ASYNC(da + (ar * QP + ac * 8) * 2, as); \
        CP_ASYNC(da + ((ar + 32) * QP + ac * 8) * 2, as + 32 * 512); \
        CP_ASYNC(da + ((ar + 64) * QP + ac * 8) * 2, as + 64 * 512); \
        CP_ASYNC(da + ((ar + 96) * QP + ac * 8) * 2, as + 96 * 512); \
        unsigned db = sBb + (st) * 9216; \
        const __half* bs = B + (size_t)(n0 + ar) * 512 + (kc) * 64 + ac * 8; \
        CP_ASYNC(db + (ar * QP + ac * 8) * 2, bs); \
        CP_ASYNC(db + ((ar + 32) * QP + ac * 8) * 2, bs + 32 * 512); \
    } while (0)

    const unsigned aq = ((wid * 16 + (lane & 15)) * QP + (lane >> 4) * 8) * 2;
    const unsigned bq = (((lane >> 4) * 8 + lr) * QP + ((lane >> 3) & 1) * 8) * 2;

    float c[8][4] = {};

    OUT_ISSUE(0, 0); CP_COMMIT();
    OUT_ISSUE(1, 1); CP_COMMIT();

    int st = 0, sti = 2;
    for (int kc = 0; kc < 8; kc++) {
        if (kc == 7) CP_WAIT0(); else CP_WAIT1();
        __syncthreads();
        if (kc < 6) { OUT_ISSUE(kc + 2, sti); CP_COMMIT(); }
        const unsigned ab = sAb + st * 18432;
        const unsigned bb = sBb + st * 9216;
        #pragma unroll
        for (int s = 0; s < 4; s++) {
            unsigned af[4];
            ldm_x4(af, ab + aq + s * 32);
            #pragma unroll
            for (int ntp = 0; ntp < 4; ntp++) {
                unsigned bf[4];
                ldm_x4(bf, bb + bq + ntp * (16 * QP * 2) + s * 32);
                mma16816(c[2 * ntp],     af, bf);
                mma16816(c[2 * ntp + 1], af, bf + 2);
            }
        }
        st = (st == 2) ? 0 : st + 1;
        sti = (sti == 2) ? 0 : sti + 1;
    }

    const int r0 = m0 + wid * 16 + gid;
    float* o0 = out + (size_t)r0 * EE;
    float* o1 = o0 + 8 * EE;
    #pragma unroll
    for (int nt = 0; nt < 8; nt++) {
        int col = n0 + nt * 8 + 2 * tig;
        float b0 = bias[col], b1 = bias[col + 1];
        *(float2*)(o0 + col) = make_float2(c[nt][0] + b0, c[nt][1] + b1);
        *(float2*)(o1 + col) = make_float2(c[nt][2] + b0, c[nt][3] + b1);
    }
}

// ---------------------------------------------------------------------------
// Launch
// ---------------------------------------------------------------------------
extern "C" void kernel_launch(void* const* d_in, const int* in_sizes, int n_in,
                              void* d_out, int out_size)
{
    const float* x      = (const float*)d_in[0];
    const float* adj    = (const float*)d_in[1];
    const float* Wqkv_w = (const float*)d_in[2];
    const float* Wqkv_b = (const float*)d_in[3];
    const float* out_w  = (const float*)d_in[4];
    const float* out_b  = (const float*)d_in[5];
    float* out = (float*)d_out;

    cudaFuncSetAttribute(qkvpack_kernel,  cudaFuncAttributeMaxDynamicSharedMemorySize, 82944);
    cudaFuncSetAttribute(attn_kernel,     cudaFuncAttributeMaxDynamicSharedMemorySize, 73728);
    cudaFuncSetAttribute(out_hmma_kernel, cudaFuncAttributeMaxDynamicSharedMemorySize, 82944);

    conv_kernel<<<2560, 256>>>(x, Wqkv_w, out_w);
    qkvpack_kernel<<<2048, 256, 82944>>>(Wqkv_b, adj);
    attn_kernel<<<dim3(SS / 128, HH, BB), 256, 73728>>>();
    out_hmma_kernel<<<dim3(8, 64), 256, 82944>>>(out_b, out);
}